// round 2
// baseline (speedup 1.0000x reference)
#include <cuda_runtime.h>
#include <cuda_bf16.h>
#include <cstdint>

// Problem constants (from reference setup_inputs):
//   input_spikes: [B=32, C=3, H=128, W=128, T=50]  float32
//   weight/gain/bias: [C,H,W] = [3,128,128]         float32 (bias unused by reference)
// Output buffer = spikes [B,C,H,W,T] ++ final_v [B,C,H,W] ++ final_reset [B,C,H,W]

#define T_STEPS 50
#define PIX_PER_BLK 128
#define SMEM_STRIDE 129            // 129 % 32 == 1 -> conflict-free column reads
#define CHW 49152                  // 3*128*128
#define TOTAL_PIX 1572864          // 32*49152
#define SPIKES_ELEMS 78643200LL    // TOTAL_PIX * T_STEPS

// decay = float32(exp(-1/4)); one_minus_decay = 1 - decay (in float32, as reference does)
__device__ __forceinline__ float lif_decay() { return 0.77880078307140486825f; }

__global__ void __launch_bounds__(PIX_PER_BLK)
lif_kernel(const float* __restrict__ x,
           const float* __restrict__ w,
           const float* __restrict__ g,
           float* __restrict__ out_spikes,
           float* __restrict__ out_final_v,
           float* __restrict__ out_final_r)
{
    __shared__ float s[T_STEPS * SMEM_STRIDE];   // 25,800 B

    const int tid = threadIdx.x;
    const long long base_pix = (long long)blockIdx.x * PIX_PER_BLK;

    // ---- Phase 1: coalesced load of this block's contiguous input region ----
    // Region = 128 pixels * 50 floats = 6400 floats = 3200 float2.
    // T=50 is even, so each float2 stays within one pixel's time series.
    const float2* gin = reinterpret_cast<const float2*>(x) + base_pix * (T_STEPS / 2);
    #pragma unroll
    for (int i = 0; i < (PIX_PER_BLK * T_STEPS / 2) / PIX_PER_BLK; ++i) {
        int idx2  = i * PIX_PER_BLK + tid;   // float2 index within region
        float2 v2 = gin[idx2];
        int gidx  = idx2 * 2;                // float index within region
        int p     = gidx / T_STEPS;          // local pixel
        int t     = gidx - p * T_STEPS;      // timestep (even)
        s[t       * SMEM_STRIDE + p] = v2.x;
        s[(t + 1) * SMEM_STRIDE + p] = v2.y;
    }
    __syncthreads();

    // ---- Phase 2: per-pixel LIF recurrence over T, in-place spike writeback ----
    const long long gp = base_pix + tid;          // global pixel index
    const int chw = (int)(gp % CHW);              // param index

    const float decay = lif_decay();
    const float omd   = 1.0f - decay;
    const float wv = w[chw];
    const float gv = g[chw];

    float v = 0.0f, r = 0.0f;
    #pragma unroll
    for (int t = 0; t < T_STEPS; ++t) {
        float xx = s[t * SMEM_STRIDE + tid];
        float wp = wv * xx;                       // weighted_psp
        v = v * decay + gv * wp * omd;            // reference op order
        float spike = (v > 1.0f) ? 1.0f : 0.0f;
        r = r * decay + spike;
        s[t * SMEM_STRIDE + tid] = spike;         // reuse buffer for output
    }
    out_final_v[gp] = v;
    out_final_r[gp] = r;
    __syncthreads();

    // ---- Phase 3: coalesced store of spikes (mirror of phase 1) ----
    float2* gout = reinterpret_cast<float2*>(out_spikes) + base_pix * (T_STEPS / 2);
    #pragma unroll
    for (int i = 0; i < (PIX_PER_BLK * T_STEPS / 2) / PIX_PER_BLK; ++i) {
        int idx2 = i * PIX_PER_BLK + tid;
        int gidx = idx2 * 2;
        int p    = gidx / T_STEPS;
        int t    = gidx - p * T_STEPS;
        float2 v2 = make_float2(s[t       * SMEM_STRIDE + p],
                                s[(t + 1) * SMEM_STRIDE + p]);
        gout[idx2] = v2;
    }
}

extern "C" void kernel_launch(void* const* d_in, const int* in_sizes, int n_in,
                              void* d_out, int out_size)
{
    const float* x = (const float*)d_in[0];   // input_spikes
    const float* w = (const float*)d_in[1];   // weight
    const float* g = (const float*)d_in[2];   // gain
    // d_in[3] = bias: unused by the reference computation

    float* out        = (float*)d_out;
    float* out_spikes = out;
    float* out_vf     = out + SPIKES_ELEMS;
    float* out_rf     = out + SPIKES_ELEMS + TOTAL_PIX;

    const int blocks = TOTAL_PIX / PIX_PER_BLK;  // 12288
    lif_kernel<<<blocks, PIX_PER_BLK>>>(x, w, g, out_spikes, out_vf, out_rf);
}

// round 3
// speedup vs baseline: 1.1873x; 1.1873x over previous
#include <cuda_runtime.h>
#include <cuda_bf16.h>
#include <cstdint>

// Problem constants (from reference setup_inputs):
//   input_spikes: [B=32, C=3, H=128, W=128, T=50]  float32
//   weight/gain/bias: [C,H,W] = [3,128,128]         float32 (bias unused)
// Output = spikes [B,C,H,W,T] ++ final_v [B,C,H,W] ++ final_reset [B,C,H,W]

#define T_STEPS      50
#define PIX_PER_BLK  128
#define REGION_FLOATS (PIX_PER_BLK * T_STEPS)   // 6400
#define REGION_BYTES  (REGION_FLOATS * 4)       // 25600 (16B multiple, 256B multiple)
#define CHW          49152                      // 3*128*128
#define TOTAL_PIX    1572864                    // 32*49152
#define SPIKES_ELEMS 78643200LL                 // TOTAL_PIX * T_STEPS

__device__ __forceinline__ float lif_decay() { return 0.77880078307140486825f; }

__global__ void __launch_bounds__(PIX_PER_BLK)
lif_kernel(const float* __restrict__ x,
           const float* __restrict__ w,
           const float* __restrict__ g,
           float* __restrict__ out_spikes,
           float* __restrict__ out_final_v,
           float* __restrict__ out_final_r)
{
    __shared__ __align__(128) float s[REGION_FLOATS];   // 25,600 B, linear gmem image
    __shared__ __align__(8)   uint64_t mbar;

    const int tid = threadIdx.x;
    const long long base_pix = (long long)blockIdx.x * PIX_PER_BLK;

    const uint32_t smem_s    = (uint32_t)__cvta_generic_to_shared(s);
    const uint32_t smem_mbar = (uint32_t)__cvta_generic_to_shared(&mbar);

    // ---- mbarrier init + TMA bulk load of the whole contiguous region ----
    if (tid == 0) {
        asm volatile("mbarrier.init.shared.b64 [%0], %1;"
                     :: "r"(smem_mbar), "r"(1) : "memory");
        asm volatile("fence.proxy.async.shared::cta;" ::: "memory");
        asm volatile("mbarrier.arrive.expect_tx.shared.b64 _, [%0], %1;"
                     :: "r"(smem_mbar), "r"(REGION_BYTES) : "memory");
        const float* src = x + base_pix * T_STEPS;
        asm volatile(
            "cp.async.bulk.shared::cta.global.mbarrier::complete_tx::bytes "
            "[%0], [%1], %2, [%3];"
            :: "r"(smem_s), "l"(src), "r"(REGION_BYTES), "r"(smem_mbar)
            : "memory");
    }
    __syncthreads();

    // ---- wait for bulk-load completion (phase parity 0) ----
    {
        uint32_t done;
        asm volatile(
            "{\n\t.reg .pred p;\n\t"
            "mbarrier.try_wait.parity.acquire.cta.shared::cta.b64 p, [%1], 0;\n\t"
            "selp.b32 %0, 1, 0, p;\n\t}"
            : "=r"(done) : "r"(smem_mbar) : "memory");
        if (!done) {
            asm volatile(
                "{\n\t.reg .pred P1;\n\t"
                "WAIT_LOOP_%=:\n\t"
                "mbarrier.try_wait.parity.acquire.cta.shared::cta.b64 P1, [%0], 0, 0x989680;\n\t"
                "@P1 bra.uni WAIT_DONE_%=;\n\t"
                "bra.uni WAIT_LOOP_%=;\n\t"
                "WAIT_DONE_%=:\n\t}"
                :: "r"(smem_mbar) : "memory");
        }
    }

    // ---- per-pixel LIF recurrence over T, spikes written back in place ----
    const long long gp  = base_pix + tid;
    const int       chw = (int)(gp % CHW);

    const float decay = lif_decay();
    const float omd   = 1.0f - decay;
    const float wv = w[chw];
    const float gv = g[chw];

    // Thread's row: byte offset tid*200 -> 8B aligned, so float2 is legal.
    float2* srow = reinterpret_cast<float2*>(s + tid * T_STEPS);

    float v = 0.0f, r = 0.0f;
    #pragma unroll
    for (int i = 0; i < T_STEPS / 2; ++i) {
        float2 xx = srow[i];

        float wp0 = wv * xx.x;
        v = v * decay + gv * wp0 * omd;          // reference op order
        float sp0 = (v > 1.0f) ? 1.0f : 0.0f;
        r = r * decay + sp0;

        float wp1 = wv * xx.y;
        v = v * decay + gv * wp1 * omd;
        float sp1 = (v > 1.0f) ? 1.0f : 0.0f;
        r = r * decay + sp1;

        srow[i] = make_float2(sp0, sp1);
    }
    out_final_v[gp] = v;
    out_final_r[gp] = r;

    __syncthreads();

    // ---- TMA bulk store of spikes back to the contiguous output region ----
    if (tid == 0) {
        // Order all threads' generic-proxy STS before the async-proxy read.
        asm volatile("fence.proxy.async.shared::cta;" ::: "memory");
        float* dst = out_spikes + base_pix * T_STEPS;
        asm volatile(
            "cp.async.bulk.global.shared::cta.bulk_group [%0], [%1], %2;"
            :: "l"(dst), "r"(smem_s), "r"(REGION_BYTES) : "memory");
        asm volatile("cp.async.bulk.commit_group;" ::: "memory");
        asm volatile("cp.async.bulk.wait_group 0;" ::: "memory");
    }
}

extern "C" void kernel_launch(void* const* d_in, const int* in_sizes, int n_in,
                              void* d_out, int out_size)
{
    const float* x = (const float*)d_in[0];   // input_spikes
    const float* w = (const float*)d_in[1];   // weight
    const float* g = (const float*)d_in[2];   // gain
    // d_in[3] = bias: unused by the reference computation

    float* out        = (float*)d_out;
    float* out_spikes = out;
    float* out_vf     = out + SPIKES_ELEMS;
    float* out_rf     = out + SPIKES_ELEMS + TOTAL_PIX;

    const int blocks = TOTAL_PIX / PIX_PER_BLK;  // 12288
    lif_kernel<<<blocks, PIX_PER_BLK>>>(x, w, g, out_spikes, out_vf, out_rf);
}